// round 11
// baseline (speedup 1.0000x reference)
#include <cuda_runtime.h>
#include <math.h>

#define NSTEP 100
#define B_TOTAL 2048
#define ELEMS_PER_CTA 8
#define THREADS 512
#define NCTAS (B_TOTAL / ELEMS_PER_CTA)   // 256

// Shared layout (float offsets):
//  w2s  [0, 13312)        w2 transposed: [c][ky][kx][oc], oc contiguous
//        prologue overlay: xs 8*256 at [0,2048), w1s at [2048,2256), b1s at [2256,2269)
//  dsum [13312, 21952)    per-k dense sums: dsum[k*576 + p*64 + oc]
//  wf2  [21952, 23104)    576 float2: wf2[p*64+oc] = {wf[0][oc*9+p], wf[1][oc*9+p]}
//  dec  [23104, 23572)    468 u32: (f2base offset)<<5 | class(0..24)
//  xch  [23572, 28180)    8 elems * 576: per-elem [contributor_half][p][32 oc slots]
//  part [28180, 28196)    8 elems * float2 FC partial (h1 -> h0)
#define OFF_DSUM 13312
#define OFF_WF2  21952
#define OFF_DEC  23104
#define OFF_XCH  23572
#define OFF_PART 28180
#define SMEM_FLOATS 28196   // 112,784 bytes; 2 CTAs fit in 228KB

// One valid position: exact fadd/fsub via fmaf(w, +-1, acc); compile-time indices.
#define A1(oy,ox) { float2 w = base[-(((oy)*4+(ox))*32)]; \
    sx[(oy)*3+(ox)] = fmaf(w.x, sgn, sx[(oy)*3+(ox)]); \
    sy[(oy)*3+(ox)] = fmaf(w.y, sgn, sy[(oy)*3+(ox)]); }
// x-class row bodies
#define RX0(oy) A1(oy,0)
#define RX1(oy) A1(oy,0) A1(oy,1)
#define RX2(oy) A1(oy,0) A1(oy,1) A1(oy,2)
#define RX3(oy) A1(oy,1) A1(oy,2)
#define RX4(oy) A1(oy,2)
// y-class row sets
#define CY0(R) R(0)
#define CY1(R) R(0) R(1)
#define CY2(R) R(0) R(1) R(2)
#define CY3(R) R(1) R(2)
#define CY4(R) R(2)

__global__ __launch_bounds__(THREADS, 2) void snn_kernel(
    const float* __restrict__ x,  const float* __restrict__ w1, const float* __restrict__ b1,
    const float* __restrict__ w2, const float* __restrict__ b2, const float* __restrict__ wf,
    const float* __restrict__ bf, float* __restrict__ out)
{
    extern __shared__ float smem[];
    float2*   wf2v  = (float2*)(smem + OFF_WF2);
    unsigned* decs  = (unsigned*)(smem + OFF_DEC);
    const float2* dsumF2 = (const float2*)(smem + OFF_DSUM);
    // prologue overlays (inside w2s region):
    float* xs  = smem;            // 8*256
    float* w1s = smem + 2048;     // 208
    float* b1s = smem + 2256;     // 13

    const int tid  = threadIdx.x;
    const int wid  = tid >> 5;
    const int lane = tid & 31;
    const int h    = wid & 1;           // half: h0 -> k 0..7, h1 -> k 8..14
    const int elem = wid >> 1;          // 0..7
    const int b    = blockIdx.x * ELEMS_PER_CTA + elem;
    const int oc   = h * 32 + lane;     // this lane's layer-2 oc for LIF/FC

    // ---- prologue stage 1: small tables + input image ----
    for (int w = tid; w < 576; w += THREADS) {
        int p = w >> 6, o = w & 63;
        wf2v[w] = make_float2(wf[o * 9 + p], wf[576 + o * 9 + p]);
    }
    for (int e = tid; e < 468; e += THREADS) {
        int c = e / 36, r = e - c * 36, iy = r / 6, ix = r - iy * 6;
        int s0i = iy * 4 + ix;
        // rectangle classes: iy -> yc, ix -> xc  (valid oy/ox sets)
        int yc = (iy == 0) ? 0 : (iy == 1) ? 1 : (iy <= 3) ? 2 : (iy == 4) ? 3 : 4;
        int xc = (ix == 0) ? 0 : (ix == 1) ? 1 : (ix <= 3) ? 2 : (ix == 4) ? 3 : 4;
        decs[e] = ((unsigned)(c * 512 + s0i * 32) << 5) | (unsigned)(yc * 5 + xc);
    }
    if (tid < 208) w1s[tid] = w1[tid];
    if (tid < 13)  b1s[tid] = b1[tid];
    {   // each warp loads half of its element's image
        float4* xs4 = (float4*)(xs + elem * 256);
        const float4* xg = (const float4*)(x + (size_t)b * 256);
        xs4[h * 32 + lane] = xg[h * 32 + lane];
    }
    __syncthreads();

    // ---- prologue stage 2: cur1 = maxpool2(conv1(x)+b1) -> registers ----
    float cur[8], v1[8];
    {
        const float* xw = xs + elem * 256;
        #pragma unroll
        for (int kk = 0; kk < 8; kk++) {
            cur[kk] = 0.f; v1[kk] = 0.f;
            if (kk < 8 - h) {
                int k = h * 8 + kk;
                int e = k * 32 + lane;
                if (e < 468) {
                    int c = e / 36, r = e - c * 36, py = r / 6, px = r - py * 6;
                    float m = -INFINITY;
                    #pragma unroll
                    for (int dy = 0; dy < 2; dy++)
                    #pragma unroll
                    for (int dx = 0; dx < 2; dx++) {
                        int iy0 = 2 * py + dy, ix0 = 2 * px + dx;
                        float s = 0.f;
                        #pragma unroll
                        for (int ky = 0; ky < 4; ky++)
                        #pragma unroll
                        for (int kx = 0; kx < 4; kx++)
                            s = fmaf(xw[(iy0 + ky) * 16 + ix0 + kx], w1s[c * 16 + ky * 4 + kx], s);
                        s = __fadd_rn(s, b1s[c]);
                        m = fmaxf(m, s);
                    }
                    cur[kk] = m;
                }
            }
        }
    }
    __syncthreads();

    // ---- prologue stage 3: w2 transpose (overwrites overlays) ----
    for (int idx = tid; idx < 13312; idx += THREADS) {   // w2[oc][c*16+kk] -> w2s[(c*16+kk)*64+oc]
        int o = idx / 208; int r = idx - o * 208;
        smem[r * 64 + o] = w2[idx];
    }
    __syncthreads();

    // ---- prologue stage 4: per-k dense weight sums ----
    for (int idx = tid; idx < 8640; idx += THREADS) {
        int k = idx / 576; int r = idx - k * 576; int p = r >> 6; int o = r & 63;
        int oy = p / 3, ox = p - oy * 3;
        int cpos = oy * 4 + ox;
        int cnt = (k == 14) ? 20 : 32;
        const unsigned MASK5[5] = {1u, 3u, 7u, 6u, 4u};
        float s = 0.f;
        for (int j = 0; j < cnt; j++) {
            unsigned d = decs[k * 32 + j];
            unsigned cls = d & 31u;
            unsigned ym = MASK5[cls / 5], xm = MASK5[cls % 5];
            if (((ym >> oy) & 1u) && ((xm >> ox) & 1u))
                s = __fadd_rn(s, smem[(d >> 5) * 2 - cpos * 64 + o]);
        }
        smem[OFF_DSUM + idx] = s;
    }
    __syncthreads();

    // ---- recurrent state ----
    float2 b2p = ((const float2*)b2)[lane];   // oc pair (2*lane, 2*lane+1) for sacc
    float v2[9], i2[9];
    #pragma unroll
    for (int p = 0; p < 9; p++) { v2[p] = 0.f; i2[p] = 0.f; }
    float v30 = 0.f, i30 = 0.f, v31 = 0.f, i31 = 0.f, so0 = 0.f, so1 = 0.f;   // h0 only
    const float bf0 = bf[0], bf1 = bf[1];
    float ft = 0.f;   // i1(t) = cur * ft;  ft' = 0.8 ft + 1 (i1 has no reset)

    float* xchE = smem + OFF_XCH + elem * 576;
    float2* partE = (float2*)(smem + OFF_PART) + elem;
    float2* outv = (float2*)(out + 2 * B_TOTAL) + b;
    const int barid = elem + 1;

    // ---- 100 timesteps ----
    for (int t = 0; t < NSTEP; t++) {
        // ===== phase A: layer-1 LIF (own k half) + accumulate sacc (full 64 oc, pair/lane)
        float sx[9], sy[9];
        #pragma unroll
        for (int p = 0; p < 9; p++) {
            sx[p] = (h == 0) ? b2p.x : 0.f;
            sy[p] = (h == 0) ? b2p.y : 0.f;
        }
        #pragma unroll
        for (int kk = 0; kk < 8; kk++) {
            if (kk < 8 - h) {
                const int k = h * 8 + kk;
                float i1v = __fmul_rn(cur[kk], ft);
                float vd = __fadd_rn(v1[kk], __fmul_rn(0.1f, __fsub_rn(i1v, v1[kk])));
                bool z = vd > 1.0f;
                v1[kk] = z ? 0.f : vd;
                unsigned m = __ballot_sync(0xffffffffu, z);
                const int cnt = (k == 14) ? 20 : 32;
                const unsigned kmask = (k == 14) ? 0xFFFFFu : 0xFFFFFFFFu;
                const unsigned* deck = decs + (k << 5);
                int n = __popc(m);
                unsigned use; float sgn;
                if (2 * n > cnt + 1) {
                    // complement: add dense sum, subtract non-spiking rows
                    const float2* dp = dsumF2 + k * 288 + lane;
                    #pragma unroll
                    for (int p = 0; p < 9; p++) {
                        float2 dv = dp[p * 32];
                        sx[p] = __fadd_rn(sx[p], dv.x);
                        sy[p] = __fadd_rn(sy[p], dv.y);
                    }
                    use = ~m & kmask; sgn = -1.0f;
                } else {
                    use = m; sgn = 1.0f;
                }
                // row walk: 25-class uniform switch, dense straight-line bodies.
                // Issues exactly the valid LDS.64 + FFMA(+-1) per row (exact vs fadd/fsub).
                while (use) {
                    int j = __ffs(use) - 1; use &= use - 1;
                    unsigned d = deck[j];
                    const float2* base = (const float2*)smem + (d >> 5) + lane;
                    switch (d & 31u) {
                        case  0: CY0(RX0) break;
                        case  1: CY0(RX1) break;
                        case  2: CY0(RX2) break;
                        case  3: CY0(RX3) break;
                        case  4: CY0(RX4) break;
                        case  5: CY1(RX0) break;
                        case  6: CY1(RX1) break;
                        case  7: CY1(RX2) break;
                        case  8: CY1(RX3) break;
                        case  9: CY1(RX4) break;
                        case 10: CY2(RX0) break;
                        case 11: CY2(RX1) break;
                        case 12: CY2(RX2) break;
                        case 13: CY2(RX3) break;
                        case 14: CY2(RX4) break;
                        case 15: CY3(RX0) break;
                        case 16: CY3(RX1) break;
                        case 17: CY3(RX2) break;
                        case 18: CY3(RX3) break;
                        case 19: CY3(RX4) break;
                        case 20: CY4(RX0) break;
                        case 21: CY4(RX1) break;
                        case 22: CY4(RX2) break;
                        case 23: CY4(RX3) break;
                        default: CY4(RX4) break;
                    }
                }
            }
        }
        ft = __fadd_rn(__fmul_rn(0.8f, ft), 1.0f);

        // write partner-oc share of own sacc to smem (16 active lanes)
        if ((lane >> 4) == (1 - h)) {
            int s = (lane & 15) << 1;
            float* dst = xchE + h * 288 + s;
            #pragma unroll
            for (int p = 0; p < 9; p++)
                *(float2*)(dst + p * 32) = make_float2(sx[p], sy[p]);
        }
        asm volatile("bar.sync %0, 64;" :: "r"(barid));   // bar A

        // ===== phase B: merge sacc for own oc; layer-2 LIF + FC (oc-split)
        float c0 = 0.f, c1 = 0.f;
        const int src = (h << 4) + (lane >> 1);
        const float* prtB = xchE + (1 - h) * 288 + lane;
        #pragma unroll
        for (int p = 0; p < 9; p++) {
            float a  = __shfl_sync(0xffffffffu, sx[p], src);
            float bb = __shfl_sync(0xffffffffu, sy[p], src);
            float own = (lane & 1) ? bb : a;
            float tot = __fadd_rn(own, prtB[p * 32]);   // (b2 + sum_h0) + sum_h1
            float vd = __fadd_rn(v2[p], __fmul_rn(0.1f, __fsub_rn(i2[p], v2[p])));
            bool z2 = vd > 1.0f;
            v2[p] = z2 ? 0.f : vd;
            i2[p] = __fadd_rn(__fmul_rn(0.8f, i2[p]), tot);
            float2 q = wf2v[p * 64 + oc];
            c0 = __fadd_rn(c0, z2 ? q.x : 0.0f);
            c1 = __fadd_rn(c1, z2 ? q.y : 0.0f);
        }
        #pragma unroll
        for (int o = 16; o > 0; o >>= 1) {
            c0 += __shfl_xor_sync(0xffffffffu, c0, o);
            c1 += __shfl_xor_sync(0xffffffffu, c1, o);
        }
        if (h == 1 && lane == 0) *partE = make_float2(c0, c1);
        asm volatile("bar.sync %0, 64;" :: "r"(barid));   // bar B

        // ===== layer 3 (h0 only)
        if (h == 0) {
            float2 pp = *partE;
            float cur30 = __fadd_rn(__fadd_rn(c0, pp.x), bf0);
            float cur31 = __fadd_rn(__fadd_rn(c1, pp.y), bf1);
            float vd0 = __fadd_rn(v30, __fmul_rn(0.1f, __fsub_rn(i30, v30)));
            float vd1 = __fadd_rn(v31, __fmul_rn(0.1f, __fsub_rn(i31, v31)));
            bool z0 = vd0 > 1.0f, z1 = vd1 > 1.0f;
            v30 = z0 ? 0.f : vd0;
            v31 = z1 ? 0.f : vd1;
            i30 = __fadd_rn(__fmul_rn(0.8f, i30), cur30);
            i31 = __fadd_rn(__fmul_rn(0.8f, i31), cur31);
            so0 += z0 ? 1.f : 0.f;
            so1 += z1 ? 1.f : 0.f;
            if (lane == 0) outv[t * B_TOTAL] = make_float2(v30, v31);
        }
    }
    if (h == 0 && lane == 0) ((float2*)out)[b] = make_float2(so0, so1);
}

extern "C" void kernel_launch(void* const* d_in, const int* in_sizes, int n_in,
                              void* d_out, int out_size) {
    const float* x  = (const float*)d_in[0];
    const float* w1 = (const float*)d_in[1];
    const float* b1 = (const float*)d_in[2];
    const float* w2 = (const float*)d_in[3];
    const float* b2 = (const float*)d_in[4];
    const float* wf = (const float*)d_in[5];
    const float* bf = (const float*)d_in[6];
    float* out = (float*)d_out;

    size_t shmem = (size_t)SMEM_FLOATS * sizeof(float);
    cudaFuncSetAttribute(snn_kernel, cudaFuncAttributeMaxDynamicSharedMemorySize, (int)shmem);
    snn_kernel<<<NCTAS, THREADS, shmem>>>(x, w1, b1, w2, b2, wf, bf, out);
}

// round 13
// speedup vs baseline: 3.5748x; 3.5748x over previous
#include <cuda_runtime.h>
#include <math.h>

#define NSTEP 100
#define B_TOTAL 2048
#define ELEMS_PER_CTA 8
#define THREADS 512
#define NCTAS (B_TOTAL / ELEMS_PER_CTA)   // 256

// Shared layout (float offsets):
//  w2s  [0, 13312)        w2 transposed: [c][ky][kx][oc], oc contiguous
//        prologue overlay: xs 8*256 at [0,2048), w1s at [2048,2256), b1s at [2256,2269)
//  dsum [13312, 21952)    per-group dense sums: dsum[k*576 + p*64 + oc]
//  wf2  [21952, 23104)    576 float2: wf2[p*64+oc] = {wf[0][oc*9+p], wf[1][oc*9+p]}
//  dec  [23104, 23572)    468 u32: float2-unit base offset of element's w2 block
//  xch  [23572, 28180)    8 elems * 576 (t-loop); prologue overlay: einfo[468] u32
//  part [28180, 28196)    8 elems * float2 FC partial (h1 -> h0)
#define OFF_DSUM 13312
#define OFF_WF2  21952
#define OFF_DEC  23104
#define OFF_XCH  23572
#define OFF_PART 28180
#define SMEM_FLOATS 28196   // 112,784 bytes; 2 CTAs fit in 228KB

// ---- class-sorted element order (computed offline from the fixed 6x6 geometry) ----
// class (yc,xc): yc(iy): {0:0,1:1,2:2,3:2,4:3,5:4}, same for xc(ix).
// elements sorted by (yc,xc,c,iy,ix); 15 groups of 32 (last has 20).
// Per group: contiguous segments with compile-time lane-masks and class bodies.

// One valid position: exact fadd/fsub via fmaf(w, +-1, acc); compile-time indices.
#define A1(oy,ox) { float2 w = base[-(((oy)*4+(ox))*32)]; \
    sx[(oy)*3+(ox)] = fmaf(w.x, sgn, sx[(oy)*3+(ox)]); \
    sy[(oy)*3+(ox)] = fmaf(w.y, sgn, sy[(oy)*3+(ox)]); }
#define RX0(oy) A1(oy,0)
#define RX1(oy) A1(oy,0) A1(oy,1)
#define RX2(oy) A1(oy,0) A1(oy,1) A1(oy,2)
#define RX3(oy) A1(oy,1) A1(oy,2)
#define RX4(oy) A1(oy,2)
#define CY0(R) R(0)
#define CY1(R) R(0) R(1)
#define CY2(R) R(0) R(1) R(2)
#define CY3(R) R(1) R(2)
#define CY4(R) R(2)

#define SEG(CMASK, CLSBODY) { unsigned sseg = use & (CMASK); \
    while (sseg) { int j = __ffs(sseg) - 1; sseg &= sseg - 1; \
        const float2* base = f2s + deck[j] + lane; CLSBODY } }

#define GSEGS_0  SEG(0x00001FFFu, CY0(RX0)) SEG(0x03FFE000u, CY0(RX1)) SEG(0xFC000000u, CY0(RX2))
#define GSEGS_1  SEG(0x000FFFFFu, CY0(RX2)) SEG(0xFFF00000u, CY0(RX3))
#define GSEGS_2  SEG(0x00000001u, CY0(RX3)) SEG(0x00003FFEu, CY0(RX4)) SEG(0x07FFC000u, CY1(RX0)) SEG(0xF8000000u, CY1(RX1))
#define GSEGS_3  SEG(0x000000FFu, CY1(RX1)) SEG(0xFFFFFF00u, CY1(RX2))
#define GSEGS_4  SEG(0x00000003u, CY1(RX2)) SEG(0x00007FFCu, CY1(RX3)) SEG(0x0FFF8000u, CY1(RX4)) SEG(0xF0000000u, CY2(RX0))
#define GSEGS_5  SEG(0x003FFFFFu, CY2(RX0)) SEG(0xFFC00000u, CY2(RX1))
#define GSEGS_6  SEG(0x0000FFFFu, CY2(RX1)) SEG(0xFFFF0000u, CY2(RX2))
#define GSEGS_7  SEG(0xFFFFFFFFu, CY2(RX2))
#define GSEGS_8  SEG(0x0000000Fu, CY2(RX2)) SEG(0x3FFFFFF0u, CY2(RX3)) SEG(0xC0000000u, CY2(RX4))
#define GSEGS_9  SEG(0x00FFFFFFu, CY2(RX4)) SEG(0xFF000000u, CY3(RX0))
#define GSEGS_10 SEG(0x0000001Fu, CY3(RX0)) SEG(0x0003FFE0u, CY3(RX1)) SEG(0xFFFC0000u, CY3(RX2))
#define GSEGS_11 SEG(0x00000FFFu, CY3(RX2)) SEG(0x01FFF000u, CY3(RX3)) SEG(0xFE000000u, CY3(RX4))
#define GSEGS_12 SEG(0x0000003Fu, CY3(RX4)) SEG(0x0007FFC0u, CY4(RX0)) SEG(0xFFF80000u, CY4(RX1))
#define GSEGS_13 SEG(0x03FFFFFFu, CY4(RX2)) SEG(0xFC000000u, CY4(RX3))
#define GSEGS_14 SEG(0x0000007Fu, CY4(RX3)) SEG(0x000FFF80u, CY4(RX4))

#define GROUP(kconst, CNT, KMASK, GSEGS) { \
    float i1v = __fmul_rn(cur[(kconst) & 7], ft); \
    float vd1_ = __fadd_rn(v1[(kconst) & 7], __fmul_rn(0.1f, __fsub_rn(i1v, v1[(kconst) & 7]))); \
    bool z_ = vd1_ > 1.0f; \
    v1[(kconst) & 7] = z_ ? 0.f : vd1_; \
    unsigned m_ = __ballot_sync(0xffffffffu, z_); \
    const unsigned* deck = decs + ((kconst) << 5); \
    int n_ = __popc(m_); \
    unsigned use; float sgn; \
    if (2 * n_ > (CNT) + 1) { \
        const float2* dp = dsumF2 + (kconst) * 288 + lane; \
        _Pragma("unroll") for (int p = 0; p < 9; p++) { \
            float2 dv = dp[p * 32]; \
            sx[p] = __fadd_rn(sx[p], dv.x); \
            sy[p] = __fadd_rn(sy[p], dv.y); } \
        use = ~m_ & (KMASK); sgn = -1.0f; \
    } else { use = m_; sgn = 1.0f; } \
    GSEGS \
}

// decode sorted index e -> (c, iy, ix); prologue-only
__device__ __forceinline__ unsigned decode_elem(int e) {
    const int ycnt[5]  = {1, 1, 2, 1, 1};
    const int ylist[5][2] = {{0,0},{1,1},{2,3},{4,4},{5,5}};
    int base = 0;
    for (int yc = 0; yc < 5; yc++)
        for (int xc = 0; xc < 5; xc++) {
            int per = ycnt[yc] * ycnt[xc];
            int sz = per * 13;
            if (e < base + sz) {
                int idx = e - base;
                int c = idx / per, rem = idx - c * per;
                int iy = ylist[yc][rem / ycnt[xc]];
                int ix = ylist[xc][rem % ycnt[xc]];
                return ((unsigned)c << 8) | ((unsigned)iy << 4) | (unsigned)ix;
            }
            base += sz;
        }
    return 0;
}

__global__ __launch_bounds__(THREADS, 2) void snn_kernel(
    const float* __restrict__ x,  const float* __restrict__ w1, const float* __restrict__ b1,
    const float* __restrict__ w2, const float* __restrict__ b2, const float* __restrict__ wf,
    const float* __restrict__ bf, float* __restrict__ out)
{
    extern __shared__ float smem[];
    float2*   wf2v  = (float2*)(smem + OFF_WF2);
    unsigned* decs  = (unsigned*)(smem + OFF_DEC);
    unsigned* einfo = (unsigned*)(smem + OFF_XCH);   // prologue overlay in xch
    const float2* dsumF2 = (const float2*)(smem + OFF_DSUM);
    const float2* f2s = (const float2*)smem;
    float* xs  = smem;            // 8*256 (prologue overlay in w2s)
    float* w1s = smem + 2048;     // 208
    float* b1s = smem + 2256;     // 13

    const int tid  = threadIdx.x;
    const int wid  = tid >> 5;
    const int lane = tid & 31;
    const int h    = wid & 1;           // half: h0 -> groups 0..7, h1 -> 8..14
    const int elem = wid >> 1;          // 0..7
    const int b    = blockIdx.x * ELEMS_PER_CTA + elem;
    const int oc   = h * 32 + lane;     // this lane's layer-2 oc for LIF/FC

    // ---- prologue stage 1: tables, element decode, input image ----
    for (int w = tid; w < 576; w += THREADS) {
        int p = w >> 6, o = w & 63;
        wf2v[w] = make_float2(wf[o * 9 + p], wf[576 + o * 9 + p]);
    }
    for (int e = tid; e < 468; e += THREADS) {
        unsigned info = decode_elem(e);
        einfo[e] = info;
        int c = info >> 8, iy = (info >> 4) & 15, ix = info & 15;
        decs[e] = (unsigned)(c * 512 + (iy * 4 + ix) * 32);   // float2 units
    }
    if (tid < 208) w1s[tid] = w1[tid];
    if (tid < 13)  b1s[tid] = b1[tid];
    {   // each warp loads half of its element's image
        float4* xs4 = (float4*)(xs + elem * 256);
        const float4* xg = (const float4*)(x + (size_t)b * 256);
        xs4[h * 32 + lane] = xg[h * 32 + lane];
    }
    __syncthreads();

    // ---- prologue stage 2: cur1 = maxpool2(conv1(x)+b1) -> registers (sorted order) ----
    float cur[8], v1[8];
    {
        const float* xw = xs + elem * 256;
        #pragma unroll
        for (int kk = 0; kk < 8; kk++) {
            cur[kk] = 0.f; v1[kk] = 0.f;
            if (kk < 8 - h) {
                int e = (h * 8 + kk) * 32 + lane;
                if (e < 468) {
                    unsigned info = einfo[e];
                    int c = info >> 8, py = (info >> 4) & 15, px = info & 15;
                    float m = -INFINITY;
                    #pragma unroll
                    for (int dy = 0; dy < 2; dy++)
                    #pragma unroll
                    for (int dx = 0; dx < 2; dx++) {
                        int iy0 = 2 * py + dy, ix0 = 2 * px + dx;
                        float s = 0.f;
                        #pragma unroll
                        for (int ky = 0; ky < 4; ky++)
                        #pragma unroll
                        for (int kx = 0; kx < 4; kx++)
                            s = fmaf(xw[(iy0 + ky) * 16 + ix0 + kx], w1s[c * 16 + ky * 4 + kx], s);
                        s = __fadd_rn(s, b1s[c]);
                        m = fmaxf(m, s);
                    }
                    cur[kk] = m;
                }
            }
        }
    }
    __syncthreads();

    // ---- prologue stage 3: w2 transpose (overwrites xs/w1s/b1s overlays) ----
    for (int idx = tid; idx < 13312; idx += THREADS) {   // w2[oc][c*16+kk] -> w2s[(c*16+kk)*64+oc]
        int o = idx / 208; int r = idx - o * 208;
        smem[r * 64 + o] = w2[idx];
    }
    __syncthreads();

    // ---- prologue stage 4: per-group dense weight sums (sorted groups) ----
    for (int idx = tid; idx < 8640; idx += THREADS) {
        int k = idx / 576; int r = idx - k * 576; int p = r >> 6; int o = r & 63;
        int oy = p / 3, ox = p - oy * 3;
        int cpos = oy * 4 + ox;
        int cnt = (k == 14) ? 20 : 32;
        float s = 0.f;
        for (int j = 0; j < cnt; j++) {
            int e = k * 32 + j;
            unsigned info = einfo[e];
            int iy = (info >> 4) & 15, ix = info & 15;
            if ((unsigned)(iy - oy) < 4u && (unsigned)(ix - ox) < 4u)
                s = __fadd_rn(s, smem[decs[e] * 2 - cpos * 64 + o]);
        }
        smem[OFF_DSUM + idx] = s;
    }
    __syncthreads();   // einfo (in xch) dead from here; xch reused below

    // ---- recurrent state ----
    float2 b2p = ((const float2*)b2)[lane];   // oc pair (2*lane, 2*lane+1) for sacc
    float v2[9], i2[9];
    #pragma unroll
    for (int p = 0; p < 9; p++) { v2[p] = 0.f; i2[p] = 0.f; }
    float v30 = 0.f, i30 = 0.f, v31 = 0.f, i31 = 0.f, so0 = 0.f, so1 = 0.f;   // h0 only
    const float bf0 = bf[0], bf1 = bf[1];
    float ft = 0.f;   // i1(t) = cur * ft;  ft' = 0.8 ft + 1 (i1 has no reset)

    float* xchE = smem + OFF_XCH + elem * 576;
    float2* partE = (float2*)(smem + OFF_PART) + elem;
    float2* outv = (float2*)(out + 2 * B_TOTAL) + b;
    const int barid = elem + 1;

    // ---- 100 timesteps ----
    for (int t = 0; t < NSTEP; t++) {
        // ===== phase A: layer-1 LIF + segment-specialized sparse accumulate
        float sx[9], sy[9];
        #pragma unroll
        for (int p = 0; p < 9; p++) {
            sx[p] = (h == 0) ? b2p.x : 0.f;
            sy[p] = (h == 0) ? b2p.y : 0.f;
        }
        if (t < NSTEP - 1) {            // phase A at t=99 only feeds dead state
            if (h == 0) {
                GROUP(0, 32, 0xFFFFFFFFu, GSEGS_0)
                GROUP(1, 32, 0xFFFFFFFFu, GSEGS_1)
                GROUP(2, 32, 0xFFFFFFFFu, GSEGS_2)
                GROUP(3, 32, 0xFFFFFFFFu, GSEGS_3)
                GROUP(4, 32, 0xFFFFFFFFu, GSEGS_4)
                GROUP(5, 32, 0xFFFFFFFFu, GSEGS_5)
                GROUP(6, 32, 0xFFFFFFFFu, GSEGS_6)
                GROUP(7, 32, 0xFFFFFFFFu, GSEGS_7)
            } else {
                GROUP(8,  32, 0xFFFFFFFFu, GSEGS_8)
                GROUP(9,  32, 0xFFFFFFFFu, GSEGS_9)
                GROUP(10, 32, 0xFFFFFFFFu, GSEGS_10)
                GROUP(11, 32, 0xFFFFFFFFu, GSEGS_11)
                GROUP(12, 32, 0xFFFFFFFFu, GSEGS_12)
                GROUP(13, 32, 0xFFFFFFFFu, GSEGS_13)
                GROUP(14, 20, 0x000FFFFFu, GSEGS_14)
            }
        }
        ft = __fadd_rn(__fmul_rn(0.8f, ft), 1.0f);

        // write partner-oc share of own sacc to smem (16 active lanes)
        if ((lane >> 4) == (1 - h)) {
            int s = (lane & 15) << 1;
            float* dst = xchE + h * 288 + s;
            #pragma unroll
            for (int p = 0; p < 9; p++)
                *(float2*)(dst + p * 32) = make_float2(sx[p], sy[p]);
        }
        asm volatile("bar.sync %0, 64;" :: "r"(barid));   // bar A

        // ===== phase B: merge sacc for own oc; layer-2 LIF + FC (oc-split)
        float c0 = 0.f, c1 = 0.f;
        const int src = (h << 4) + (lane >> 1);
        const float* prtB = xchE + (1 - h) * 288 + lane;
        #pragma unroll
        for (int p = 0; p < 9; p++) {
            float a  = __shfl_sync(0xffffffffu, sx[p], src);
            float bb = __shfl_sync(0xffffffffu, sy[p], src);
            float own = (lane & 1) ? bb : a;
            float tot = __fadd_rn(own, prtB[p * 32]);   // (b2 + sum_h0) + sum_h1
            float vd = __fadd_rn(v2[p], __fmul_rn(0.1f, __fsub_rn(i2[p], v2[p])));
            bool z2 = vd > 1.0f;
            v2[p] = z2 ? 0.f : vd;
            i2[p] = __fadd_rn(__fmul_rn(0.8f, i2[p]), tot);
            float2 q = wf2v[p * 64 + oc];
            c0 = __fadd_rn(c0, z2 ? q.x : 0.0f);
            c1 = __fadd_rn(c1, z2 ? q.y : 0.0f);
        }
        #pragma unroll
        for (int o = 16; o > 0; o >>= 1) {
            c0 += __shfl_xor_sync(0xffffffffu, c0, o);
            c1 += __shfl_xor_sync(0xffffffffu, c1, o);
        }
        if (h == 1 && lane == 0) *partE = make_float2(c0, c1);
        asm volatile("bar.sync %0, 64;" :: "r"(barid));   // bar B

        // ===== layer 3 (h0 only)
        if (h == 0) {
            float2 pp = *partE;
            float cur30 = __fadd_rn(__fadd_rn(c0, pp.x), bf0);
            float cur31 = __fadd_rn(__fadd_rn(c1, pp.y), bf1);
            float vd0 = __fadd_rn(v30, __fmul_rn(0.1f, __fsub_rn(i30, v30)));
            float vd1 = __fadd_rn(v31, __fmul_rn(0.1f, __fsub_rn(i31, v31)));
            bool z0 = vd0 > 1.0f, z1 = vd1 > 1.0f;
            v30 = z0 ? 0.f : vd0;
            v31 = z1 ? 0.f : vd1;
            i30 = __fadd_rn(__fmul_rn(0.8f, i30), cur30);
            i31 = __fadd_rn(__fmul_rn(0.8f, i31), cur31);
            so0 += z0 ? 1.f : 0.f;
            so1 += z1 ? 1.f : 0.f;
            if (lane == 0) outv[t * B_TOTAL] = make_float2(v30, v31);
        }
    }
    if (h == 0 && lane == 0) ((float2*)out)[b] = make_float2(so0, so1);
}

extern "C" void kernel_launch(void* const* d_in, const int* in_sizes, int n_in,
                              void* d_out, int out_size) {
    const float* x  = (const float*)d_in[0];
    const float* w1 = (const float*)d_in[1];
    const float* b1 = (const float*)d_in[2];
    const float* w2 = (const float*)d_in[3];
    const float* b2 = (const float*)d_in[4];
    const float* wf = (const float*)d_in[5];
    const float* bf = (const float*)d_in[6];
    float* out = (float*)d_out;

    size_t shmem = (size_t)SMEM_FLOATS * sizeof(float);
    cudaFuncSetAttribute(snn_kernel, cudaFuncAttributeMaxDynamicSharedMemorySize, (int)shmem);
    snn_kernel<<<NCTAS, THREADS, shmem>>>(x, w1, b1, w2, b2, wf, bf, out);
}